// round 7
// baseline (speedup 1.0000x reference)
#include <cuda_runtime.h>
#include <cuda_bf16.h>
#include <cstdint>

constexpr int NB  = 8;
constexpr int CH  = 512;
constexpr int HW  = 4096;
constexpr int HW2 = 2048;
constexpr int CO  = 256;

// ---------------- device scratch ----------------
__device__ __align__(256) float g_S [(size_t)NB * HW2 * HW2];

__device__ __align__(256) __nv_bfloat16 g_qTh[(size_t)NB * HW * CH], g_qTl[(size_t)NB * HW * CH];
__device__ __align__(256) __nv_bfloat16 g_kTh[(size_t)NB * HW * CH], g_kTl[(size_t)NB * HW * CH];
__device__ __align__(256) __nv_bfloat16 g_vTh[(size_t)NB * HW * CH];
__device__ __align__(256) __nv_bfloat16 g_Wph[CO * CH], g_Wpl[CO * CH];
__device__ __align__(256) __nv_bfloat16 g_Wth[CO * CH], g_Wtl[CO * CH];
__device__ __align__(256) __nv_bfloat16 g_Wgh[CO * CH], g_Wgl[CO * CH];
__device__ __align__(256) __nv_bfloat16 g_Wmh[CH * CO], g_Wml[CH * CO];
__device__ __align__(256) __nv_bfloat16 g_gh [(size_t)NB * CH * HW2], g_gl [(size_t)NB * CH * HW2];
__device__ __align__(256) __nv_bfloat16 g_pTh[(size_t)NB * HW2 * CH], g_pTl[(size_t)NB * HW2 * CH];
__device__ __align__(256) __nv_bfloat16 g_tTh[(size_t)NB * HW2 * CH], g_tTl[(size_t)NB * HW2 * CH];
__device__ __align__(256) __nv_bfloat16 g_Sh [(size_t)NB * HW2 * HW2];
__device__ __align__(256) __nv_bfloat16 g_y3h[(size_t)NB * HW * CO];

// ---------------- helpers ----------------
__device__ __forceinline__ uint32_t s2u(const void* p) {
    uint32_t a;
    asm("{ .reg .u64 t; cvta.to.shared.u64 t, %1; cvt.u32.u64 %0, t; }" : "=r"(a) : "l"(p));
    return a;
}
__device__ __forceinline__ void bsplit(float v, __nv_bfloat16& h, __nv_bfloat16& l) {
    h = __float2bfloat16(v);
    l = __float2bfloat16(v - __bfloat162float(h));
}
__device__ __forceinline__ void ldsm4(uint32_t* r, uint32_t addr) {
    asm volatile("ldmatrix.sync.aligned.m8n8.x4.shared.b16 {%0,%1,%2,%3}, [%4];"
                 : "=r"(r[0]), "=r"(r[1]), "=r"(r[2]), "=r"(r[3]) : "r"(addr));
}
__device__ __forceinline__ void mma16816(float* d, const uint32_t* a, uint32_t b0, uint32_t b1) {
    asm volatile("mma.sync.aligned.m16n8k16.row.col.f32.bf16.bf16.f32 "
                 "{%0,%1,%2,%3}, {%4,%5,%6,%7}, {%8,%9}, {%0,%1,%2,%3};"
                 : "+f"(d[0]), "+f"(d[1]), "+f"(d[2]), "+f"(d[3])
                 : "r"(a[0]), "r"(a[1]), "r"(a[2]), "r"(a[3]), "r"(b0), "r"(b1));
}
__device__ __forceinline__ void cpasync16(uint32_t s, const void* g) {
    asm volatile("cp.async.cg.shared.global [%0], [%1], 16;" :: "r"(s), "l"(g));
}
#define CP_COMMIT() asm volatile("cp.async.commit_group;" ::: "memory")
#define CP_WAIT1()  asm volatile("cp.async.wait_group 1;" ::: "memory")
#define CP_WAIT0()  asm volatile("cp.async.wait_group 0;" ::: "memory")

// smem per stage (32 KB): Ah @0, Al @8192, Bh @16384, Bl @24576.
// Row = 64 B (32 bf16), chunk = 16 B, swizzle: chunk ^= (row>>1)&3
template <int TERMS>
__device__ __forceinline__ void load_stage(uint32_t sbase,
    const __nv_bfloat16* pAh, const __nv_bfloat16* pAl,
    const __nv_bfloat16* pBh, const __nv_bfloat16* pBl,
    int Ktot, int kofs, int tid)
{
    const int row = tid >> 1;
    const int c0 = (tid & 1) * 2;
    const long long gofs = (long long)row * Ktot + kofs;
    #pragma unroll
    for (int s = 0; s < 2; s++) {
        const int c = c0 + s;
        const uint32_t soff = row * 64 + ((c ^ ((row >> 1) & 3)) << 4);
        cpasync16(sbase +         soff, pAh + gofs + c * 8);
        cpasync16(sbase + 8192  + soff, pAl + gofs + c * 8);
        cpasync16(sbase + 16384 + soff, pBh + gofs + c * 8);
        if (TERMS == 3)
            cpasync16(sbase + 24576 + soff, pBl + gofs + c * 8);
    }
}

// ---------------------------------------------------------------------------
// Split-bf16 tensor-core GEMM (mma.sync), 3-stage cp.async pipeline.
// D(128x128 fp32 tile) = (Ah+Al)(MxK) @ (Bh+Bl)^T(NxK), A/B K-major bf16.
// TERMS: 3 = hh + h*bl + al*bh; 2 = hh + al*bh (B_lo never touched).
// EPI: 0 = fp32 store
//      1 = split-bf16 hi/lo store (row-major)
//      2 = fp32 + r1 + r2 (residual)
//      3 = transposed split hi/lo store with k' = h1*256+o  (conv -> pT')
//      4 = transposed hi store with parity-grouped cols     (apply -> y3)
// ---------------------------------------------------------------------------
template <int EPI, int TERMS>
__global__ void __launch_bounds__(256) mma_gemm(
    const __nv_bfloat16* __restrict__ Ah, const __nv_bfloat16* __restrict__ Al,
    const __nv_bfloat16* __restrict__ Bh, const __nv_bfloat16* __restrict__ Bl,
    float* __restrict__ C, __nv_bfloat16* __restrict__ Ch, __nv_bfloat16* __restrict__ Cl,
    int Ktot, int ldc,
    long long sA, long long sB, long long sC,
    const float* __restrict__ r1, const float* __restrict__ r2)
{
    extern __shared__ __align__(1024) char sm[];
    const int tid = threadIdx.x;
    const int wid = tid >> 5, lane = tid & 31;
    const uint32_t sb = s2u(sm);

    const int m0 = blockIdx.y * 128;
    const int n0 = blockIdx.x * 128;
    const long long bz = blockIdx.z;

    const __nv_bfloat16* pAh = Ah + bz * sA + (long long)m0 * Ktot;
    const __nv_bfloat16* pAl = Al + bz * sA + (long long)m0 * Ktot;
    const __nv_bfloat16* pBh = Bh + bz * sB + (long long)n0 * Ktot;
    const __nv_bfloat16* pBl = (TERMS == 3) ? (Bl + bz * sB + (long long)n0 * Ktot) : nullptr;

    const int wm = (wid >> 1) * 32;
    const int wn = (wid & 1) * 64;

    float acc[2][8][4];
    #pragma unroll
    for (int i = 0; i < 2; i++)
        #pragma unroll
        for (int j = 0; j < 8; j++)
            #pragma unroll
            for (int t = 0; t < 4; t++) acc[i][j][t] = 0.0f;

    const int nch = Ktot >> 5;
    load_stage<TERMS>(sb, pAh, pAl, pBh, pBl, Ktot, 0, tid);
    CP_COMMIT();
    load_stage<TERMS>(sb + 32768, pAh, pAl, pBh, pBl, Ktot, 32, tid);
    CP_COMMIT();

    uint32_t stage = 0;
    uint32_t nstage = 2;
    for (int ic = 0; ic < nch; ic++) {
        CP_WAIT1();
        __syncthreads();
        if (ic + 2 < nch) {
            load_stage<TERMS>(sb + nstage * 32768, pAh, pAl, pBh, pBl,
                              Ktot, (ic + 2) << 5, tid);
        }
        CP_COMMIT();
        nstage = (nstage == 2) ? 0 : nstage + 1;

        const uint32_t st = sb + stage * 32768;
        stage = (stage == 2) ? 0 : stage + 1;
        #pragma unroll
        for (int kk = 0; kk < 32; kk += 16) {
            const int kc = (kk >> 3) + (lane >> 4);
            uint32_t a_h[2][4], a_l[2][4];
            #pragma unroll
            for (int mi = 0; mi < 2; mi++) {
                const int row = wm + mi * 16 + (lane & 15);
                const uint32_t ad = st + row * 64 + ((kc ^ ((row >> 1) & 3)) << 4);
                ldsm4(a_h[mi], ad);
                ldsm4(a_l[mi], ad + 8192);
            }
            #pragma unroll
            for (int jj = 0; jj < 4; jj++) {
                const int row = wn + jj * 16 + (lane & 15);
                const uint32_t bd = st + 16384 + row * 64 + ((kc ^ ((row >> 1) & 3)) << 4);
                uint32_t bh[4], bl[4];
                ldsm4(bh, bd);
                if (TERMS == 3) ldsm4(bl, bd + 8192);
                #pragma unroll
                for (int mi = 0; mi < 2; mi++) {
                    mma16816(acc[mi][jj * 2],     a_h[mi], bh[0], bh[2]);
                    mma16816(acc[mi][jj * 2 + 1], a_h[mi], bh[1], bh[3]);
                    if (TERMS == 3) {
                        mma16816(acc[mi][jj * 2],     a_h[mi], bl[0], bl[2]);
                        mma16816(acc[mi][jj * 2 + 1], a_h[mi], bl[1], bl[3]);
                    }
                    mma16816(acc[mi][jj * 2],     a_l[mi], bh[0], bh[2]);
                    mma16816(acc[mi][jj * 2 + 1], a_l[mi], bh[1], bh[3]);
                }
            }
        }
    }

    const int g = lane >> 2, tg = lane & 3;
    const long long cbz = bz * sC;

    if (EPI == 3 || EPI == 4) {
        // stage tile fp32 in smem (pad 129), then transposed coalesced stores
        CP_WAIT0();
        __syncthreads();
        float* Dsm = (float*)sm;
        #pragma unroll
        for (int mi = 0; mi < 2; mi++)
            #pragma unroll
            for (int j = 0; j < 8; j++)
                #pragma unroll
                for (int h = 0; h < 2; h++) {
                    const int row = wm + mi * 16 + g + h * 8;
                    const int col = wn + j * 8 + tg * 2;
                    Dsm[row * 129 + col]     = acc[mi][j][h * 2];
                    Dsm[row * 129 + col + 1] = acc[mi][j][h * 2 + 1];
                }
        __syncthreads();

        if (EPI == 3) {
            // out[n][h1*256 + o] (hi+lo), n = (n0&2047)+n_loc, o in [m0, m0+128)
            const int h1 = n0 >> 11;
            const int xb = n0 & 2047;
            const int n_loc = tid >> 1;
            const int half = tid & 1;
            const long long ob = cbz + (long long)(xb + n_loc) * ldc + (h1 * 256 + m0) + half * 64;
            #pragma unroll
            for (int i = 0; i < 64; i += 2) {
                const float v0 = Dsm[(half * 64 + i)     * 129 + n_loc];
                const float v1 = Dsm[(half * 64 + i + 1) * 129 + n_loc];
                __nv_bfloat16 h0, l0, hh1, ll1;
                bsplit(v0, h0, l0); bsplit(v1, hh1, ll1);
                *(__nv_bfloat162*)(Ch + ob + i) = __halves2bfloat162(h0, hh1);
                *(__nv_bfloat162*)(Cl + ob + i) = __halves2bfloat162(l0, ll1);
            }
        } else {
            // y3[x][o2], x = (c&1)*2048 + m, o2 = c>>1; tile rows c=[m0,m0+128), cols m=[n0,n0+128)
            const int m_loc = tid >> 1;
            const int h1 = tid & 1;
            const long long ob = cbz + (long long)(h1 * 2048 + n0 + m_loc) * ldc + (m0 >> 1);
            #pragma unroll
            for (int o2 = 0; o2 < 64; o2 += 2) {
                const float v0 = Dsm[(2 * o2 + h1)     * 129 + m_loc];
                const float v1 = Dsm[(2 * o2 + 2 + h1) * 129 + m_loc];
                *(__nv_bfloat162*)(Ch + ob + o2) =
                    __halves2bfloat162(__float2bfloat16(v0), __float2bfloat16(v1));
            }
        }
        return;
    }

    // direct epilogues (0/1/2)
    #pragma unroll
    for (int mi = 0; mi < 2; mi++) {
        #pragma unroll
        for (int j = 0; j < 8; j++) {
            const int row = m0 + wm + mi * 16 + g;
            const int col = n0 + wn + j * 8 + tg * 2;
            #pragma unroll
            for (int h = 0; h < 2; h++) {
                const long long idx = cbz + (long long)(row + h * 8) * ldc + col;
                const float d0 = acc[mi][j][h * 2];
                const float d1 = acc[mi][j][h * 2 + 1];
                if (EPI == 0) {
                    *(float2*)(C + idx) = make_float2(d0, d1);
                } else if (EPI == 2) {
                    const float2 a = *(const float2*)(r1 + idx);
                    const float2 b = *(const float2*)(r2 + idx);
                    *(float2*)(C + idx) = make_float2(d0 + a.x + b.x, d1 + a.y + b.y);
                } else {
                    __nv_bfloat16 h0, l0, hh1, ll1;
                    bsplit(d0, h0, l0); bsplit(d1, hh1, ll1);
                    *(__nv_bfloat162*)(Ch + idx) = __halves2bfloat162(h0, hh1);
                    *(__nv_bfloat162*)(Cl + idx) = __halves2bfloat162(l0, ll1);
                }
            }
        }
    }
}

// ---------------------------------------------------------------------------
// conversion kernels
// ---------------------------------------------------------------------------
__global__ void __launch_bounds__(256) split_kernel(const float* __restrict__ in,
                                                    __nv_bfloat16* __restrict__ hi,
                                                    __nv_bfloat16* __restrict__ lo, int n) {
    const int i = blockIdx.x * 256 + threadIdx.x;
    if (i < n) {
        __nv_bfloat16 h, l;
        bsplit(in[i], h, l);
        hi[i] = h; lo[i] = l;
    }
}

// (b, 512, 4096) -> (b, 4096, 512); lo written only if ol != nullptr
__global__ void __launch_bounds__(256) tsplit_kernel(const float* __restrict__ in,
                                                     __nv_bfloat16* __restrict__ oh,
                                                     __nv_bfloat16* __restrict__ ol) {
    __shared__ float T[32][33];
    const int tx = threadIdx.x & 31, ty = threadIdx.x >> 5;
    const int x0 = blockIdx.x * 32, c0 = blockIdx.y * 32;
    const float* I = in + (size_t)blockIdx.z * CH * HW;
    #pragma unroll
    for (int r = 0; r < 4; r++)
        T[ty + r * 8][tx] = I[(size_t)(c0 + ty + r * 8) * HW + x0 + tx];
    __syncthreads();
    const size_t ob = (size_t)blockIdx.z * HW * CH;
    #pragma unroll
    for (int r = 0; r < 4; r++) {
        const float v = T[tx][ty + r * 8];
        __nv_bfloat16 h, l;
        bsplit(v, h, l);
        const size_t o = ob + (size_t)(x0 + ty + r * 8) * CH + c0 + tx;
        oh[o] = h;
        if (ol) ol[o] = l;
    }
}

// row softmax (rows of length 2048) -> bf16 hi only
__global__ void __launch_bounds__(256) softmax_split_kernel(const float* __restrict__ S,
                                                            __nv_bfloat16* __restrict__ Sh) {
    const size_t row = blockIdx.x;
    const float* p = S + row * HW2;
    const int tid = threadIdx.x;

    float4 v0 = ((const float4*)p)[tid];
    float4 v1 = ((const float4*)p)[tid + 256];

    float mx = fmaxf(fmaxf(fmaxf(v0.x, v0.y), fmaxf(v0.z, v0.w)),
                     fmaxf(fmaxf(v1.x, v1.y), fmaxf(v1.z, v1.w)));
    __shared__ float red[8];
    #pragma unroll
    for (int o = 16; o > 0; o >>= 1) mx = fmaxf(mx, __shfl_xor_sync(0xffffffffu, mx, o));
    if ((tid & 31) == 0) red[tid >> 5] = mx;
    __syncthreads();
    mx = red[0];
    #pragma unroll
    for (int i = 1; i < 8; i++) mx = fmaxf(mx, red[i]);
    __syncthreads();

    v0.x = __expf(v0.x - mx); v0.y = __expf(v0.y - mx);
    v0.z = __expf(v0.z - mx); v0.w = __expf(v0.w - mx);
    v1.x = __expf(v1.x - mx); v1.y = __expf(v1.y - mx);
    v1.z = __expf(v1.z - mx); v1.w = __expf(v1.w - mx);

    float sum = v0.x + v0.y + v0.z + v0.w + v1.x + v1.y + v1.z + v1.w;
    #pragma unroll
    for (int o = 16; o > 0; o >>= 1) sum += __shfl_xor_sync(0xffffffffu, sum, o);
    if ((tid & 31) == 0) red[tid >> 5] = sum;
    __syncthreads();
    sum = red[0];
    #pragma unroll
    for (int i = 1; i < 8; i++) sum += red[i];

    const float inv = 1.0f / sum;
    __nv_bfloat162* ph = (__nv_bfloat162*)(Sh + row * HW2);
    ph[tid * 2 + 0] = __halves2bfloat162(__float2bfloat16(v0.x * inv), __float2bfloat16(v0.y * inv));
    ph[tid * 2 + 1] = __halves2bfloat162(__float2bfloat16(v0.z * inv), __float2bfloat16(v0.w * inv));
    ph[(tid + 256) * 2 + 0] = __halves2bfloat162(__float2bfloat16(v1.x * inv), __float2bfloat16(v1.y * inv));
    ph[(tid + 256) * 2 + 1] = __halves2bfloat162(__float2bfloat16(v1.z * inv), __float2bfloat16(v1.w * inv));
}

// ---------------------------------------------------------------------------
extern "C" void kernel_launch(void* const* d_in, const int* in_sizes, int n_in,
                              void* d_out, int out_size)
{
    const float* q    = (const float*)d_in[0];
    const float* k    = (const float*)d_in[1];
    const float* v    = (const float*)d_in[2];
    const float* Wphi = (const float*)d_in[3];
    const float* Wth  = (const float*)d_in[4];
    const float* Wg   = (const float*)d_in[5];
    const float* Wm   = (const float*)d_in[6];
    float* out = (float*)d_out;

    constexpr int SMEM = 98304;   // 3 stages x 32 KB (epilogue reuses)
    cudaFuncSetAttribute(mma_gemm<3,3>, cudaFuncAttributeMaxDynamicSharedMemorySize, SMEM);
    cudaFuncSetAttribute(mma_gemm<1,2>, cudaFuncAttributeMaxDynamicSharedMemorySize, SMEM);
    cudaFuncSetAttribute(mma_gemm<0,3>, cudaFuncAttributeMaxDynamicSharedMemorySize, SMEM);
    cudaFuncSetAttribute(mma_gemm<4,2>, cudaFuncAttributeMaxDynamicSharedMemorySize, SMEM);
    cudaFuncSetAttribute(mma_gemm<2,2>, cudaFuncAttributeMaxDynamicSharedMemorySize, SMEM);

    float *S;
    cudaGetSymbolAddress((void**)&S, g_S);
    __nv_bfloat16 *qTh, *qTl, *kTh, *kTl, *vTh;
    __nv_bfloat16 *Wph, *Wpl, *Wthh, *Wtl, *Wgh, *Wgl, *Wmh, *Wml;
    __nv_bfloat16 *gh, *gl, *pTh, *pTl, *tTh, *tTl, *Sh, *y3h;
    cudaGetSymbolAddress((void**)&qTh, g_qTh); cudaGetSymbolAddress((void**)&qTl, g_qTl);
    cudaGetSymbolAddress((void**)&kTh, g_kTh); cudaGetSymbolAddress((void**)&kTl, g_kTl);
    cudaGetSymbolAddress((void**)&vTh, g_vTh);
    cudaGetSymbolAddress((void**)&Wph, g_Wph); cudaGetSymbolAddress((void**)&Wpl, g_Wpl);
    cudaGetSymbolAddress((void**)&Wthh, g_Wth); cudaGetSymbolAddress((void**)&Wtl, g_Wtl);
    cudaGetSymbolAddress((void**)&Wgh, g_Wgh); cudaGetSymbolAddress((void**)&Wgl, g_Wgl);
    cudaGetSymbolAddress((void**)&Wmh, g_Wmh); cudaGetSymbolAddress((void**)&Wml, g_Wml);
    cudaGetSymbolAddress((void**)&gh, g_gh);   cudaGetSymbolAddress((void**)&gl, g_gl);
    cudaGetSymbolAddress((void**)&pTh, g_pTh); cudaGetSymbolAddress((void**)&pTl, g_pTl);
    cudaGetSymbolAddress((void**)&tTh, g_tTh); cudaGetSymbolAddress((void**)&tTl, g_tTl);
    cudaGetSymbolAddress((void**)&Sh, g_Sh);
    cudaGetSymbolAddress((void**)&y3h, g_y3h);

    const dim3 blk(256);
    const long long sX  = (long long)CH * HW;    // q/k/v/out batch stride
    const long long sT  = (long long)HW * CH;    // qT/kT/vT
    const long long sP  = (long long)CO * HW;    // g (==CH*HW2)
    const long long sPT = (long long)HW2 * CH;   // pT'/tT'
    const long long sS  = (long long)HW2 * HW2;  // scores
    const long long sY3 = (long long)HW * CO;    // y3

    // 0) weight splits
    split_kernel<<<CO * CH / 256, blk>>>(Wphi, Wph, Wpl, CO * CH);
    split_kernel<<<CO * CH / 256, blk>>>(Wth,  Wthh, Wtl, CO * CH);
    split_kernel<<<CO * CH / 256, blk>>>(Wg,   Wgh, Wgl, CO * CH);
    split_kernel<<<CH * CO / 256, blk>>>(Wm,   Wmh, Wml, CH * CO);

    // 1) input transpose+split (v: hi only)
    tsplit_kernel<<<dim3(HW / 32, CH / 32, NB), blk>>>(q, qTh, qTl);
    tsplit_kernel<<<dim3(HW / 32, CH / 32, NB), blk>>>(k, kTh, kTl);
    tsplit_kernel<<<dim3(HW / 32, CH / 32, NB), blk>>>(v, vTh, nullptr);

    // 2) 1x1 convs: phi/theta (3-term, EPI=3: write pT'/tT' transposed hi/lo directly);
    //    g (2-term, EPI=1: row-major split)
    mma_gemm<3,3><<<dim3(HW / 128, CO / 128, NB), blk, SMEM>>>(Wph, Wpl, qTh, qTl, nullptr, pTh, pTl,
                                                               CH, CH, 0, sT, sPT, nullptr, nullptr);
    mma_gemm<3,3><<<dim3(HW / 128, CO / 128, NB), blk, SMEM>>>(Wthh, Wtl, kTh, kTl, nullptr, tTh, tTl,
                                                               CH, CH, 0, sT, sPT, nullptr, nullptr);
    mma_gemm<1,2><<<dim3(HW / 128, CO / 128, NB), blk, SMEM>>>(Wgh, Wgl, vTh, nullptr, nullptr, gh, gl,
                                                               CH, HW, 0, sT, sP, nullptr, nullptr);

    // 3) scores (3-term): S[m,n] = sum_k' pT'[m,k'] * tT'[n,k']
    mma_gemm<0,3><<<dim3(HW2 / 128, HW2 / 128, NB), blk, SMEM>>>(pTh, pTl, tTh, tTl, S, nullptr, nullptr,
                                                                 CH, HW2, sPT, sPT, sS, nullptr, nullptr);

    // 4) row softmax -> bf16 hi
    softmax_split_kernel<<<NB * HW2, blk>>>(S, Sh);

    // 5) attn apply (2-term, EPI=4): writes y3h transposed directly
    mma_gemm<4,2><<<dim3(HW2 / 128, CH / 128, NB), blk, SMEM>>>(gh, gl, Sh, nullptr, nullptr, y3h, nullptr,
                                                                HW2, CO, sP, sS, sY3, nullptr, nullptr);

    // 6) mask conv (2-term) + residual: out = Wm @ y3 + q + v
    mma_gemm<2,2><<<dim3(HW / 128, CH / 128, NB), blk, SMEM>>>(Wmh, Wml, y3h, nullptr, out, nullptr, nullptr,
                                                               CO, HW, 0, sY3, sX, q, v);
}

// round 8
// speedup vs baseline: 1.1080x; 1.1080x over previous
#include <cuda_runtime.h>
#include <cuda_bf16.h>
#include <cstdint>

constexpr int NB  = 8;
constexpr int CH  = 512;
constexpr int HW  = 4096;
constexpr int HW2 = 2048;
constexpr int CO  = 256;

// ---------------- device scratch ----------------
__device__ __align__(256) float g_S [(size_t)NB * HW2 * HW2];

__device__ __align__(256) __nv_bfloat16 g_qTh[(size_t)NB * HW * CH], g_qTl[(size_t)NB * HW * CH];
__device__ __align__(256) __nv_bfloat16 g_kTh[(size_t)NB * HW * CH], g_kTl[(size_t)NB * HW * CH];
__device__ __align__(256) __nv_bfloat16 g_vTh[(size_t)NB * HW * CH];
__device__ __align__(256) __nv_bfloat16 g_Wph[CO * CH], g_Wpl[CO * CH];
__device__ __align__(256) __nv_bfloat16 g_Wth[CO * CH], g_Wtl[CO * CH];
__device__ __align__(256) __nv_bfloat16 g_Wgh[CO * CH], g_Wgl[CO * CH];
__device__ __align__(256) __nv_bfloat16 g_Wmh[CH * CO], g_Wml[CH * CO];
__device__ __align__(256) __nv_bfloat16 g_gh [(size_t)NB * CH * HW2], g_gl [(size_t)NB * CH * HW2];
__device__ __align__(256) __nv_bfloat16 g_pTh[(size_t)NB * HW2 * CH], g_pTl[(size_t)NB * HW2 * CH];
__device__ __align__(256) __nv_bfloat16 g_tTh[(size_t)NB * HW2 * CH], g_tTl[(size_t)NB * HW2 * CH];
__device__ __align__(256) __nv_bfloat16 g_Sh [(size_t)NB * HW2 * HW2];
__device__ __align__(256) __nv_bfloat16 g_y3h[(size_t)NB * HW * CO];

// ---------------- helpers ----------------
__device__ __forceinline__ uint32_t s2u(const void* p) {
    uint32_t a;
    asm("{ .reg .u64 t; cvta.to.shared.u64 t, %1; cvt.u32.u64 %0, t; }" : "=r"(a) : "l"(p));
    return a;
}
__device__ __forceinline__ void bsplit(float v, __nv_bfloat16& h, __nv_bfloat16& l) {
    h = __float2bfloat16(v);
    l = __float2bfloat16(v - __bfloat162float(h));
}
__device__ __forceinline__ void ldsm4(uint32_t* r, uint32_t addr) {
    asm volatile("ldmatrix.sync.aligned.m8n8.x4.shared.b16 {%0,%1,%2,%3}, [%4];"
                 : "=r"(r[0]), "=r"(r[1]), "=r"(r[2]), "=r"(r[3]) : "r"(addr));
}
__device__ __forceinline__ void mma16816(float* d, const uint32_t* a, uint32_t b0, uint32_t b1) {
    asm volatile("mma.sync.aligned.m16n8k16.row.col.f32.bf16.bf16.f32 "
                 "{%0,%1,%2,%3}, {%4,%5,%6,%7}, {%8,%9}, {%0,%1,%2,%3};"
                 : "+f"(d[0]), "+f"(d[1]), "+f"(d[2]), "+f"(d[3])
                 : "r"(a[0]), "r"(a[1]), "r"(a[2]), "r"(a[3]), "r"(b0), "r"(b1));
}
__device__ __forceinline__ void cpasync16(uint32_t s, const void* g) {
    asm volatile("cp.async.cg.shared.global [%0], [%1], 16;" :: "r"(s), "l"(g));
}
#define CP_COMMIT() asm volatile("cp.async.commit_group;" ::: "memory")
#define CP_WAIT1()  asm volatile("cp.async.wait_group 1;" ::: "memory")
#define CP_WAIT0()  asm volatile("cp.async.wait_group 0;" ::: "memory")

// smem per stage (32 KB): Ah @0, Al @8192, Bh @16384, Bl @24576.
// Row = 64 B (32 bf16), chunk = 16 B, swizzle: chunk ^= (row>>1)&3
template <int TERMS>
__device__ __forceinline__ void load_stage(uint32_t sbase,
    const __nv_bfloat16* pAh, const __nv_bfloat16* pAl,
    const __nv_bfloat16* pBh, const __nv_bfloat16* pBl,
    int Ktot, int kofs, int tid)
{
    const int row = tid >> 1;
    const int c0 = (tid & 1) * 2;
    const long long gofs = (long long)row * Ktot + kofs;
    #pragma unroll
    for (int s = 0; s < 2; s++) {
        const int c = c0 + s;
        const uint32_t soff = row * 64 + ((c ^ ((row >> 1) & 3)) << 4);
        cpasync16(sbase +         soff, pAh + gofs + c * 8);
        cpasync16(sbase + 8192  + soff, pAl + gofs + c * 8);
        cpasync16(sbase + 16384 + soff, pBh + gofs + c * 8);
        if (TERMS == 3)
            cpasync16(sbase + 24576 + soff, pBl + gofs + c * 8);
    }
}

// ---------------------------------------------------------------------------
// Split-bf16 tensor-core GEMM (mma.sync), 3-stage cp.async pipeline.
// D(128x128 fp32 tile) = (Ah+Al)(MxK) @ (Bh+Bl)^T(NxK), A/B K-major bf16.
// TERMS: 3 = hh + h*bl + al*bh; 2 = hh + al*bh (B_lo never touched).
// EPI: 0 = fp32 store
//      1 = split-bf16 hi/lo store (row-major)
//      2 = fp32 + r1 + r2 (residual)
//      3 = transposed split hi/lo store with k' = h1*256+o  (conv -> pT')
//      4 = transposed hi store with parity-grouped cols     (apply -> y3)
// ---------------------------------------------------------------------------
template <int EPI, int TERMS>
__global__ void __launch_bounds__(256) mma_gemm(
    const __nv_bfloat16* __restrict__ Ah, const __nv_bfloat16* __restrict__ Al,
    const __nv_bfloat16* __restrict__ Bh, const __nv_bfloat16* __restrict__ Bl,
    float* __restrict__ C, __nv_bfloat16* __restrict__ Ch, __nv_bfloat16* __restrict__ Cl,
    int Ktot, int ldc,
    long long sA, long long sB, long long sC,
    const float* __restrict__ r1, const float* __restrict__ r2)
{
    extern __shared__ __align__(1024) char sm[];
    const int tid = threadIdx.x;
    const int wid = tid >> 5, lane = tid & 31;
    const uint32_t sb = s2u(sm);

    const int m0 = blockIdx.y * 128;
    const int n0 = blockIdx.x * 128;
    const long long bz = blockIdx.z;

    const __nv_bfloat16* pAh = Ah + bz * sA + (long long)m0 * Ktot;
    const __nv_bfloat16* pAl = Al + bz * sA + (long long)m0 * Ktot;
    const __nv_bfloat16* pBh = Bh + bz * sB + (long long)n0 * Ktot;
    const __nv_bfloat16* pBl = (TERMS == 3) ? (Bl + bz * sB + (long long)n0 * Ktot) : nullptr;

    const int wm = (wid >> 1) * 32;
    const int wn = (wid & 1) * 64;

    float acc[2][8][4];
    #pragma unroll
    for (int i = 0; i < 2; i++)
        #pragma unroll
        for (int j = 0; j < 8; j++)
            #pragma unroll
            for (int t = 0; t < 4; t++) acc[i][j][t] = 0.0f;

    const int nch = Ktot >> 5;
    load_stage<TERMS>(sb, pAh, pAl, pBh, pBl, Ktot, 0, tid);
    CP_COMMIT();
    load_stage<TERMS>(sb + 32768, pAh, pAl, pBh, pBl, Ktot, 32, tid);
    CP_COMMIT();

    uint32_t stage = 0;
    uint32_t nstage = 2;
    for (int ic = 0; ic < nch; ic++) {
        CP_WAIT1();
        __syncthreads();
        if (ic + 2 < nch) {
            load_stage<TERMS>(sb + nstage * 32768, pAh, pAl, pBh, pBl,
                              Ktot, (ic + 2) << 5, tid);
        }
        CP_COMMIT();
        nstage = (nstage == 2) ? 0 : nstage + 1;

        const uint32_t st = sb + stage * 32768;
        stage = (stage == 2) ? 0 : stage + 1;
        #pragma unroll
        for (int kk = 0; kk < 32; kk += 16) {
            const int kc = (kk >> 3) + (lane >> 4);
            uint32_t a_h[2][4], a_l[2][4];
            #pragma unroll
            for (int mi = 0; mi < 2; mi++) {
                const int row = wm + mi * 16 + (lane & 15);
                const uint32_t ad = st + row * 64 + ((kc ^ ((row >> 1) & 3)) << 4);
                ldsm4(a_h[mi], ad);
                ldsm4(a_l[mi], ad + 8192);
            }
            #pragma unroll
            for (int jj = 0; jj < 4; jj++) {
                const int row = wn + jj * 16 + (lane & 15);
                const uint32_t bd = st + 16384 + row * 64 + ((kc ^ ((row >> 1) & 3)) << 4);
                uint32_t bh[4], bl[4];
                ldsm4(bh, bd);
                if (TERMS == 3) ldsm4(bl, bd + 8192);
                #pragma unroll
                for (int mi = 0; mi < 2; mi++) {
                    mma16816(acc[mi][jj * 2],     a_h[mi], bh[0], bh[2]);
                    mma16816(acc[mi][jj * 2 + 1], a_h[mi], bh[1], bh[3]);
                    if (TERMS == 3) {
                        mma16816(acc[mi][jj * 2],     a_h[mi], bl[0], bl[2]);
                        mma16816(acc[mi][jj * 2 + 1], a_h[mi], bl[1], bl[3]);
                    }
                    mma16816(acc[mi][jj * 2],     a_l[mi], bh[0], bh[2]);
                    mma16816(acc[mi][jj * 2 + 1], a_l[mi], bh[1], bh[3]);
                }
            }
        }
    }

    const int g = lane >> 2, tg = lane & 3;
    const long long cbz = bz * sC;

    if (EPI == 3 || EPI == 4) {
        // stage tile fp32 in smem [row(m) * 129 + col(n)], then transposed
        // COALESCED stores: warps own whole output rows, 16B per lane.
        CP_WAIT0();
        __syncthreads();
        float* Dsm = (float*)sm;
        #pragma unroll
        for (int mi = 0; mi < 2; mi++)
            #pragma unroll
            for (int j = 0; j < 8; j++)
                #pragma unroll
                for (int h = 0; h < 2; h++) {
                    const int row = wm + mi * 16 + g + h * 8;
                    const int col = wn + j * 8 + tg * 2;
                    Dsm[row * 129 + col]     = acc[mi][j][h * 2];
                    Dsm[row * 129 + col + 1] = acc[mi][j][h * 2 + 1];
                }
        __syncthreads();

        if (EPI == 3) {
            // out[n][h1*256 + o], hi+lo. Row = 128 bf16 = 256B = 16 lanes x 16B.
            const int h1 = n0 >> 11;
            const int xb = n0 & 2047;
            const int lane16 = lane & 15;
            const int sub = lane >> 4;                 // 2 rows per warp per pass
            #pragma unroll
            for (int p = 0; p < 8; p++) {
                const int n_loc = p * 16 + wid * 2 + sub;
                __align__(16) __nv_bfloat16 hbuf[8], lbuf[8];
                #pragma unroll
                for (int j = 0; j < 8; j++)
                    bsplit(Dsm[(lane16 * 8 + j) * 129 + n_loc], hbuf[j], lbuf[j]);
                const long long ob = cbz + (long long)(xb + n_loc) * ldc
                                   + h1 * 256 + m0 + lane16 * 8;
                *(uint4*)(Ch + ob) = *(uint4*)hbuf;
                *(uint4*)(Cl + ob) = *(uint4*)lbuf;
            }
        } else {
            // y3[h1*2048 + n0 + m][m0/2 + o2], hi only.
            // 256 output rows (h1,m_loc) x 64 cols = 128B = 8 lanes x 16B.
            const int lane8 = lane & 7;
            const int rsub = lane >> 3;                // 4 rows per warp per pass
            #pragma unroll
            for (int p = 0; p < 8; p++) {
                const int R = p * 32 + wid * 4 + rsub; // 0..255
                const int h1 = R >> 7;
                const int m_loc = R & 127;
                __align__(16) __nv_bfloat16 hbuf[8];
                #pragma unroll
                for (int j = 0; j < 8; j++)
                    hbuf[j] = __float2bfloat16(Dsm[(2 * (lane8 * 8 + j) + h1) * 129 + m_loc]);
                const long long ob = cbz + (long long)(h1 * 2048 + n0 + m_loc) * ldc
                                   + (m0 >> 1) + lane8 * 8;
                *(uint4*)(Ch + ob) = *(uint4*)hbuf;
            }
        }
        return;
    }

    // direct epilogues (0/1/2)
    #pragma unroll
    for (int mi = 0; mi < 2; mi++) {
        #pragma unroll
        for (int j = 0; j < 8; j++) {
            const int row = m0 + wm + mi * 16 + g;
            const int col = n0 + wn + j * 8 + tg * 2;
            #pragma unroll
            for (int h = 0; h < 2; h++) {
                const long long idx = cbz + (long long)(row + h * 8) * ldc + col;
                const float d0 = acc[mi][j][h * 2];
                const float d1 = acc[mi][j][h * 2 + 1];
                if (EPI == 0) {
                    *(float2*)(C + idx) = make_float2(d0, d1);
                } else if (EPI == 2) {
                    const float2 a = *(const float2*)(r1 + idx);
                    const float2 b = *(const float2*)(r2 + idx);
                    *(float2*)(C + idx) = make_float2(d0 + a.x + b.x, d1 + a.y + b.y);
                } else {
                    __nv_bfloat16 h0, l0, hh1, ll1;
                    bsplit(d0, h0, l0); bsplit(d1, hh1, ll1);
                    *(__nv_bfloat162*)(Ch + idx) = __halves2bfloat162(h0, hh1);
                    *(__nv_bfloat162*)(Cl + idx) = __halves2bfloat162(l0, ll1);
                }
            }
        }
    }
}

// ---------------------------------------------------------------------------
// conversion kernels
// ---------------------------------------------------------------------------
// all 4 weight splits in one launch (each segment is CO*CH = CH*CO elements)
__global__ void __launch_bounds__(256) split4_kernel(
    const float* __restrict__ s0, const float* __restrict__ s1,
    const float* __restrict__ s2, const float* __restrict__ s3,
    __nv_bfloat16* __restrict__ h0, __nv_bfloat16* __restrict__ l0,
    __nv_bfloat16* __restrict__ h1, __nv_bfloat16* __restrict__ l1,
    __nv_bfloat16* __restrict__ h2, __nv_bfloat16* __restrict__ l2,
    __nv_bfloat16* __restrict__ h3, __nv_bfloat16* __restrict__ l3)
{
    const int i = blockIdx.x * 256 + threadIdx.x;
    const int wsel = blockIdx.y;
    const float* s = (wsel == 0) ? s0 : (wsel == 1) ? s1 : (wsel == 2) ? s2 : s3;
    __nv_bfloat16* hh = (wsel == 0) ? h0 : (wsel == 1) ? h1 : (wsel == 2) ? h2 : h3;
    __nv_bfloat16* ll = (wsel == 0) ? l0 : (wsel == 1) ? l1 : (wsel == 2) ? l2 : l3;
    __nv_bfloat16 h, l;
    bsplit(s[i], h, l);
    hh[i] = h; ll[i] = l;
}

// (b, 512, 4096) -> (b, 4096, 512); lo written only if ol != nullptr
__global__ void __launch_bounds__(256) tsplit_kernel(const float* __restrict__ in,
                                                     __nv_bfloat16* __restrict__ oh,
                                                     __nv_bfloat16* __restrict__ ol) {
    __shared__ float T[32][33];
    const int tx = threadIdx.x & 31, ty = threadIdx.x >> 5;
    const int x0 = blockIdx.x * 32, c0 = blockIdx.y * 32;
    const float* I = in + (size_t)blockIdx.z * CH * HW;
    #pragma unroll
    for (int r = 0; r < 4; r++)
        T[ty + r * 8][tx] = I[(size_t)(c0 + ty + r * 8) * HW + x0 + tx];
    __syncthreads();
    const size_t ob = (size_t)blockIdx.z * HW * CH;
    #pragma unroll
    for (int r = 0; r < 4; r++) {
        const float v = T[tx][ty + r * 8];
        __nv_bfloat16 h, l;
        bsplit(v, h, l);
        const size_t o = ob + (size_t)(x0 + ty + r * 8) * CH + c0 + tx;
        oh[o] = h;
        if (ol) ol[o] = l;
    }
}

// row softmax (rows of length 2048) -> bf16 hi only
__global__ void __launch_bounds__(256) softmax_split_kernel(const float* __restrict__ S,
                                                            __nv_bfloat16* __restrict__ Sh) {
    const size_t row = blockIdx.x;
    const float* p = S + row * HW2;
    const int tid = threadIdx.x;

    float4 v0 = ((const float4*)p)[tid];
    float4 v1 = ((const float4*)p)[tid + 256];

    float mx = fmaxf(fmaxf(fmaxf(v0.x, v0.y), fmaxf(v0.z, v0.w)),
                     fmaxf(fmaxf(v1.x, v1.y), fmaxf(v1.z, v1.w)));
    __shared__ float red[8];
    #pragma unroll
    for (int o = 16; o > 0; o >>= 1) mx = fmaxf(mx, __shfl_xor_sync(0xffffffffu, mx, o));
    if ((tid & 31) == 0) red[tid >> 5] = mx;
    __syncthreads();
    mx = red[0];
    #pragma unroll
    for (int i = 1; i < 8; i++) mx = fmaxf(mx, red[i]);
    __syncthreads();

    v0.x = __expf(v0.x - mx); v0.y = __expf(v0.y - mx);
    v0.z = __expf(v0.z - mx); v0.w = __expf(v0.w - mx);
    v1.x = __expf(v1.x - mx); v1.y = __expf(v1.y - mx);
    v1.z = __expf(v1.z - mx); v1.w = __expf(v1.w - mx);

    float sum = v0.x + v0.y + v0.z + v0.w + v1.x + v1.y + v1.z + v1.w;
    #pragma unroll
    for (int o = 16; o > 0; o >>= 1) sum += __shfl_xor_sync(0xffffffffu, sum, o);
    if ((tid & 31) == 0) red[tid >> 5] = sum;
    __syncthreads();
    sum = red[0];
    #pragma unroll
    for (int i = 1; i < 8; i++) sum += red[i];

    const float inv = 1.0f / sum;
    __nv_bfloat162* ph = (__nv_bfloat162*)(Sh + row * HW2);
    ph[tid * 2 + 0] = __halves2bfloat162(__float2bfloat16(v0.x * inv), __float2bfloat16(v0.y * inv));
    ph[tid * 2 + 1] = __halves2bfloat162(__float2bfloat16(v0.z * inv), __float2bfloat16(v0.w * inv));
    ph[(tid + 256) * 2 + 0] = __halves2bfloat162(__float2bfloat16(v1.x * inv), __float2bfloat16(v1.y * inv));
    ph[(tid + 256) * 2 + 1] = __halves2bfloat162(__float2bfloat16(v1.z * inv), __float2bfloat16(v1.w * inv));
}

// ---------------------------------------------------------------------------
extern "C" void kernel_launch(void* const* d_in, const int* in_sizes, int n_in,
                              void* d_out, int out_size)
{
    const float* q    = (const float*)d_in[0];
    const float* k    = (const float*)d_in[1];
    const float* v    = (const float*)d_in[2];
    const float* Wphi = (const float*)d_in[3];
    const float* Wth  = (const float*)d_in[4];
    const float* Wg   = (const float*)d_in[5];
    const float* Wm   = (const float*)d_in[6];
    float* out = (float*)d_out;

    constexpr int SMEM = 98304;   // 3 stages x 32 KB (epilogue reuses)
    cudaFuncSetAttribute(mma_gemm<3,3>, cudaFuncAttributeMaxDynamicSharedMemorySize, SMEM);
    cudaFuncSetAttribute(mma_gemm<1,2>, cudaFuncAttributeMaxDynamicSharedMemorySize, SMEM);
    cudaFuncSetAttribute(mma_gemm<0,3>, cudaFuncAttributeMaxDynamicSharedMemorySize, SMEM);
    cudaFuncSetAttribute(mma_gemm<4,2>, cudaFuncAttributeMaxDynamicSharedMemorySize, SMEM);
    cudaFuncSetAttribute(mma_gemm<2,2>, cudaFuncAttributeMaxDynamicSharedMemorySize, SMEM);

    float *S;
    cudaGetSymbolAddress((void**)&S, g_S);
    __nv_bfloat16 *qTh, *qTl, *kTh, *kTl, *vTh;
    __nv_bfloat16 *Wph, *Wpl, *Wthh, *Wtl, *Wgh, *Wgl, *Wmh, *Wml;
    __nv_bfloat16 *gh, *gl, *pTh, *pTl, *tTh, *tTl, *Sh, *y3h;
    cudaGetSymbolAddress((void**)&qTh, g_qTh); cudaGetSymbolAddress((void**)&qTl, g_qTl);
    cudaGetSymbolAddress((void**)&kTh, g_kTh); cudaGetSymbolAddress((void**)&kTl, g_kTl);
    cudaGetSymbolAddress((void**)&vTh, g_vTh);
    cudaGetSymbolAddress((void**)&Wph, g_Wph); cudaGetSymbolAddress((void**)&Wpl, g_Wpl);
    cudaGetSymbolAddress((void**)&Wthh, g_Wth); cudaGetSymbolAddress((void**)&Wtl, g_Wtl);
    cudaGetSymbolAddress((void**)&Wgh, g_Wgh); cudaGetSymbolAddress((void**)&Wgl, g_Wgl);
    cudaGetSymbolAddress((void**)&Wmh, g_Wmh); cudaGetSymbolAddress((void**)&Wml, g_Wml);
    cudaGetSymbolAddress((void**)&gh, g_gh);   cudaGetSymbolAddress((void**)&gl, g_gl);
    cudaGetSymbolAddress((void**)&pTh, g_pTh); cudaGetSymbolAddress((void**)&pTl, g_pTl);
    cudaGetSymbolAddress((void**)&tTh, g_tTh); cudaGetSymbolAddress((void**)&tTl, g_tTl);
    cudaGetSymbolAddress((void**)&Sh, g_Sh);
    cudaGetSymbolAddress((void**)&y3h, g_y3h);

    const dim3 blk(256);
    const long long sX  = (long long)CH * HW;    // q/k/v/out batch stride
    const long long sT  = (long long)HW * CH;    // qT/kT/vT
    const long long sP  = (long long)CO * HW;    // g (==CH*HW2)
    const long long sPT = (long long)HW2 * CH;   // pT'/tT'
    const long long sS  = (long long)HW2 * HW2;  // scores
    const long long sY3 = (long long)HW * CO;    // y3

    // 0) all weight splits in one launch
    split4_kernel<<<dim3(CO * CH / 256, 4), blk>>>(Wphi, Wth, Wg, Wm,
                                                   Wph, Wpl, Wthh, Wtl,
                                                   Wgh, Wgl, Wmh, Wml);

    // 1) input transpose+split (v: hi only)
    tsplit_kernel<<<dim3(HW / 32, CH / 32, NB), blk>>>(q, qTh, qTl);
    tsplit_kernel<<<dim3(HW / 32, CH / 32, NB), blk>>>(k, kTh, kTl);
    tsplit_kernel<<<dim3(HW / 32, CH / 32, NB), blk>>>(v, vTh, nullptr);

    // 2) 1x1 convs: phi/theta (3-term, EPI=3: write pT'/tT' transposed hi/lo directly);
    //    g (2-term, EPI=1: row-major split)
    mma_gemm<3,3><<<dim3(HW / 128, CO / 128, NB), blk, SMEM>>>(Wph, Wpl, qTh, qTl, nullptr, pTh, pTl,
                                                               CH, CH, 0, sT, sPT, nullptr, nullptr);
    mma_gemm<3,3><<<dim3(HW / 128, CO / 128, NB), blk, SMEM>>>(Wthh, Wtl, kTh, kTl, nullptr, tTh, tTl,
                                                               CH, CH, 0, sT, sPT, nullptr, nullptr);
    mma_gemm<1,2><<<dim3(HW / 128, CO / 128, NB), blk, SMEM>>>(Wgh, Wgl, vTh, nullptr, nullptr, gh, gl,
                                                               CH, HW, 0, sT, sP, nullptr, nullptr);

    // 3) scores (3-term): S[m,n] = sum_k' pT'[m,k'] * tT'[n,k']
    mma_gemm<0,3><<<dim3(HW2 / 128, HW2 / 128, NB), blk, SMEM>>>(pTh, pTl, tTh, tTl, S, nullptr, nullptr,
                                                                 CH, HW2, sPT, sPT, sS, nullptr, nullptr);

    // 4) row softmax -> bf16 hi
    softmax_split_kernel<<<NB * HW2, blk>>>(S, Sh);

    // 5) attn apply (2-term, EPI=4): writes y3h transposed directly
    mma_gemm<4,2><<<dim3(HW2 / 128, CH / 128, NB), blk, SMEM>>>(gh, gl, Sh, nullptr, nullptr, y3h, nullptr,
                                                                HW2, CO, sP, sS, sY3, nullptr, nullptr);

    // 6) mask conv (2-term) + residual: out = Wm @ y3 + q + v
    mma_gemm<2,2><<<dim3(HW / 128, CH / 128, NB), blk, SMEM>>>(Wmh, Wml, y3h, nullptr, out, nullptr, nullptr,
                                                               CO, HW, 0, sY3, sX, q, v);
}

// round 10
// speedup vs baseline: 1.6255x; 1.4671x over previous
#include <cuda_runtime.h>
#include <cuda_fp16.h>
#include <cstdint>

constexpr int NB  = 8;
constexpr int CH  = 512;
constexpr int HW  = 4096;
constexpr int HW2 = 2048;
constexpr int CO  = 256;

// ---------------- device scratch ----------------
__device__ __align__(256) float g_S [(size_t)NB * HW2 * HW2];

__device__ __align__(256) __half g_qTh[(size_t)NB * HW * CH];
__device__ __align__(256) __half g_kTh[(size_t)NB * HW * CH];
__device__ __align__(256) __half g_vTh[(size_t)NB * HW * CH];
__device__ __align__(256) __half g_Wph[CO * CH], g_Wpl[CO * CH];
__device__ __align__(256) __half g_Wth[CO * CH], g_Wtl[CO * CH];
__device__ __align__(256) __half g_Wgh[CO * CH], g_Wgl[CO * CH];
__device__ __align__(256) __half g_Wmh[CH * CO], g_Wml[CH * CO];
__device__ __align__(256) __half g_gh [(size_t)NB * CH * HW2];
__device__ __align__(256) __half g_pTh[(size_t)NB * HW2 * CH], g_pTl[(size_t)NB * HW2 * CH];
__device__ __align__(256) __half g_tTh[(size_t)NB * HW2 * CH];
__device__ __align__(256) __half g_Sh [(size_t)NB * HW2 * HW2];
__device__ __align__(256) __half g_y3h[(size_t)NB * HW * CO];

// ---------------- helpers ----------------
__device__ __forceinline__ uint32_t s2u(const void* p) {
    uint32_t a;
    asm("{ .reg .u64 t; cvta.to.shared.u64 t, %1; cvt.u32.u64 %0, t; }" : "=r"(a) : "l"(p));
    return a;
}
__device__ __forceinline__ void hsplit(float v, __half& h, __half& l) {
    h = __float2half(v);
    l = __float2half(v - __half2float(h));
}
__device__ __forceinline__ void ldsm4(uint32_t* r, uint32_t addr) {
    asm volatile("ldmatrix.sync.aligned.m8n8.x4.shared.b16 {%0,%1,%2,%3}, [%4];"
                 : "=r"(r[0]), "=r"(r[1]), "=r"(r[2]), "=r"(r[3]) : "r"(addr));
}
__device__ __forceinline__ void mma16816(float* d, const uint32_t* a, uint32_t b0, uint32_t b1) {
    asm volatile("mma.sync.aligned.m16n8k16.row.col.f32.f16.f16.f32 "
                 "{%0,%1,%2,%3}, {%4,%5,%6,%7}, {%8,%9}, {%0,%1,%2,%3};"
                 : "+f"(d[0]), "+f"(d[1]), "+f"(d[2]), "+f"(d[3])
                 : "r"(a[0]), "r"(a[1]), "r"(a[2]), "r"(a[3]), "r"(b0), "r"(b1));
}
__device__ __forceinline__ void cpasync16(uint32_t s, const void* g) {
    asm volatile("cp.async.cg.shared.global [%0], [%1], 16;" :: "r"(s), "l"(g));
}
#define CP_COMMIT() asm volatile("cp.async.commit_group;" ::: "memory")
#define CP_WAIT1()  asm volatile("cp.async.wait_group 1;" ::: "memory")
#define CP_WAIT0()  asm volatile("cp.async.wait_group 0;" ::: "memory")

// smem per stage (32 KB stride): Ah @0, Al @8192 (TERMS==2 only), Bh @16384.
// Row = 64 B (32 fp16), chunk = 16 B, swizzle: chunk ^= (row>>1)&3
template <int TERMS>
__device__ __forceinline__ void load_stage(uint32_t sbase,
    const __half* pAh, const __half* pAl, const __half* pBh,
    int Ktot, int kofs, int tid)
{
    const int row = tid >> 1;
    const int c0 = (tid & 1) * 2;
    const long long gofs = (long long)row * Ktot + kofs;
    #pragma unroll
    for (int s = 0; s < 2; s++) {
        const int c = c0 + s;
        const uint32_t soff = row * 64 + ((c ^ ((row >> 1) & 3)) << 4);
        cpasync16(sbase +         soff, pAh + gofs + c * 8);
        if (TERMS == 2)
            cpasync16(sbase + 8192 + soff, pAl + gofs + c * 8);
        cpasync16(sbase + 16384 + soff, pBh + gofs + c * 8);
    }
}

// ---------------------------------------------------------------------------
// Split-fp16 tensor-core GEMM (mma.sync), 3-stage cp.async pipeline.
// D(128x128 fp32 tile) = (Ah[+Al])(MxK) @ Bh^T(NxK), fp16 K-major.
// TERMS: 2 = hh + lh; 1 = hh only. (B lo never exists.)
// EPI: 0 = fp32 store (scores)
//      1 = row-major hi store (g conv)
//      2 = fp32 + r1 + r2 residual (mask)
//      3 = transposed hi+lo store, k' = h1*256+o (phi conv -> pT)
//      5 = transposed hi store,    k' = h1*256+o (theta conv -> tT)
//      4 = transposed hi store, parity-grouped cols (apply -> y3)
// ---------------------------------------------------------------------------
template <int EPI, int TERMS>
__global__ void __launch_bounds__(256) mma_gemm(
    const __half* __restrict__ Ah, const __half* __restrict__ Al,
    const __half* __restrict__ Bh,
    float* __restrict__ C, __half* __restrict__ Ch, __half* __restrict__ Cl,
    int Ktot, int ldc,
    long long sA, long long sB, long long sC,
    const float* __restrict__ r1, const float* __restrict__ r2)
{
    extern __shared__ __align__(1024) char sm[];
    const int tid = threadIdx.x;
    const int wid = tid >> 5, lane = tid & 31;
    const uint32_t sb = s2u(sm);

    const int m0 = blockIdx.y * 128;
    const int n0 = blockIdx.x * 128;
    const long long bz = blockIdx.z;

    const __half* pAh = Ah + bz * sA + (long long)m0 * Ktot;
    const __half* pAl = (TERMS == 2) ? (Al + bz * sA + (long long)m0 * Ktot) : nullptr;
    const __half* pBh = Bh + bz * sB + (long long)n0 * Ktot;

    const int wm = (wid >> 1) * 32;
    const int wn = (wid & 1) * 64;

    float acc[2][8][4];
    #pragma unroll
    for (int i = 0; i < 2; i++)
        #pragma unroll
        for (int j = 0; j < 8; j++)
            #pragma unroll
            for (int t = 0; t < 4; t++) acc[i][j][t] = 0.0f;

    const int nch = Ktot >> 5;
    load_stage<TERMS>(sb, pAh, pAl, pBh, Ktot, 0, tid);
    CP_COMMIT();
    load_stage<TERMS>(sb + 32768, pAh, pAl, pBh, Ktot, 32, tid);
    CP_COMMIT();

    uint32_t stage = 0;
    uint32_t nstage = 2;
    for (int ic = 0; ic < nch; ic++) {
        CP_WAIT1();
        __syncthreads();
        if (ic + 2 < nch) {
            load_stage<TERMS>(sb + nstage * 32768, pAh, pAl, pBh,
                              Ktot, (ic + 2) << 5, tid);
        }
        CP_COMMIT();
        nstage = (nstage == 2) ? 0 : nstage + 1;

        const uint32_t st = sb + stage * 32768;
        stage = (stage == 2) ? 0 : stage + 1;
        #pragma unroll
        for (int kk = 0; kk < 32; kk += 16) {
            const int kc = (kk >> 3) + (lane >> 4);
            uint32_t a_h[2][4], a_l[2][4];
            #pragma unroll
            for (int mi = 0; mi < 2; mi++) {
                const int row = wm + mi * 16 + (lane & 15);
                const uint32_t ad = st + row * 64 + ((kc ^ ((row >> 1) & 3)) << 4);
                ldsm4(a_h[mi], ad);
                if (TERMS == 2) ldsm4(a_l[mi], ad + 8192);
            }
            #pragma unroll
            for (int jj = 0; jj < 4; jj++) {
                const int row = wn + jj * 16 + (lane & 15);
                const uint32_t bd = st + 16384 + row * 64 + ((kc ^ ((row >> 1) & 3)) << 4);
                uint32_t bh[4];
                ldsm4(bh, bd);
                #pragma unroll
                for (int mi = 0; mi < 2; mi++) {
                    mma16816(acc[mi][jj * 2],     a_h[mi], bh[0], bh[2]);
                    mma16816(acc[mi][jj * 2 + 1], a_h[mi], bh[1], bh[3]);
                    if (TERMS == 2) {
                        mma16816(acc[mi][jj * 2],     a_l[mi], bh[0], bh[2]);
                        mma16816(acc[mi][jj * 2 + 1], a_l[mi], bh[1], bh[3]);
                    }
                }
            }
        }
    }

    const int g = lane >> 2, tg = lane & 3;
    const long long cbz = bz * sC;

    if (EPI == 3 || EPI == 4 || EPI == 5) {
        // stage tile fp32 in smem [row(m) * 129 + col(n)], transposed coalesced stores
        CP_WAIT0();
        __syncthreads();
        float* Dsm = (float*)sm;
        #pragma unroll
        for (int mi = 0; mi < 2; mi++)
            #pragma unroll
            for (int j = 0; j < 8; j++)
                #pragma unroll
                for (int h = 0; h < 2; h++) {
                    const int row = wm + mi * 16 + g + h * 8;
                    const int col = wn + j * 8 + tg * 2;
                    Dsm[row * 129 + col]     = acc[mi][j][h * 2];
                    Dsm[row * 129 + col + 1] = acc[mi][j][h * 2 + 1];
                }
        __syncthreads();

        if (EPI == 3 || EPI == 5) {
            // out[n][h1*256 + o]; row = 128 fp16 = 256B = 16 lanes x 16B.
            const int h1 = n0 >> 11;
            const int xb = n0 & 2047;
            const int lane16 = lane & 15;
            const int sub = lane >> 4;                 // 2 rows per warp per pass
            #pragma unroll
            for (int p = 0; p < 8; p++) {
                const int n_loc = p * 16 + wid * 2 + sub;
                __align__(16) __half hbuf[8], lbuf[8];
                #pragma unroll
                for (int j = 0; j < 8; j++) {
                    if (EPI == 3) hsplit(Dsm[(lane16 * 8 + j) * 129 + n_loc], hbuf[j], lbuf[j]);
                    else          hbuf[j] = __float2half(Dsm[(lane16 * 8 + j) * 129 + n_loc]);
                }
                const long long ob = cbz + (long long)(xb + n_loc) * ldc
                                   + h1 * 256 + m0 + lane16 * 8;
                *(uint4*)(Ch + ob) = *(uint4*)hbuf;
                if (EPI == 3) *(uint4*)(Cl + ob) = *(uint4*)lbuf;
            }
        } else {
            // y3[h1*2048 + n0 + m][m0/2 + o2]; row = 64 fp16 = 128B = 8 lanes x 16B.
            const int lane8 = lane & 7;
            const int rsub = lane >> 3;                // 4 rows per warp per pass
            #pragma unroll
            for (int p = 0; p < 8; p++) {
                const int R = p * 32 + wid * 4 + rsub; // 0..255
                const int h1 = R >> 7;
                const int m_loc = R & 127;
                __align__(16) __half hbuf[8];
                #pragma unroll
                for (int j = 0; j < 8; j++)
                    hbuf[j] = __float2half(Dsm[(2 * (lane8 * 8 + j) + h1) * 129 + m_loc]);
                const long long ob = cbz + (long long)(h1 * 2048 + n0 + m_loc) * ldc
                                   + (m0 >> 1) + lane8 * 8;
                *(uint4*)(Ch + ob) = *(uint4*)hbuf;
            }
        }
        return;
    }

    // direct epilogues (0/1/2)
    #pragma unroll
    for (int mi = 0; mi < 2; mi++) {
        #pragma unroll
        for (int j = 0; j < 8; j++) {
            const int row = m0 + wm + mi * 16 + g;
            const int col = n0 + wn + j * 8 + tg * 2;
            #pragma unroll
            for (int h = 0; h < 2; h++) {
                const long long idx = cbz + (long long)(row + h * 8) * ldc + col;
                const float d0 = acc[mi][j][h * 2];
                const float d1 = acc[mi][j][h * 2 + 1];
                if (EPI == 0) {
                    *(float2*)(C + idx) = make_float2(d0, d1);
                } else if (EPI == 2) {
                    const float2 a = *(const float2*)(r1 + idx);
                    const float2 b = *(const float2*)(r2 + idx);
                    *(float2*)(C + idx) = make_float2(d0 + a.x + b.x, d1 + a.y + b.y);
                } else {
                    *(__half2*)(Ch + idx) =
                        __halves2half2(__float2half(d0), __float2half(d1));
                }
            }
        }
    }
}

// ---------------------------------------------------------------------------
// conversion kernels
// ---------------------------------------------------------------------------
// all 4 weight splits in one launch
__global__ void __launch_bounds__(256) split4_kernel(
    const float* __restrict__ s0, const float* __restrict__ s1,
    const float* __restrict__ s2, const float* __restrict__ s3,
    __half* __restrict__ h0, __half* __restrict__ l0,
    __half* __restrict__ h1, __half* __restrict__ l1,
    __half* __restrict__ h2, __half* __restrict__ l2,
    __half* __restrict__ h3, __half* __restrict__ l3)
{
    const int i = blockIdx.x * 256 + threadIdx.x;
    const int wsel = blockIdx.y;
    const float* s = (wsel == 0) ? s0 : (wsel == 1) ? s1 : (wsel == 2) ? s2 : s3;
    __half* hh = (wsel == 0) ? h0 : (wsel == 1) ? h1 : (wsel == 2) ? h2 : h3;
    __half* ll = (wsel == 0) ? l0 : (wsel == 1) ? l1 : (wsel == 2) ? l2 : l3;
    __half h, l;
    hsplit(s[i], h, l);
    hh[i] = h; ll[i] = l;
}

// (b, 512, 4096) -> (b, 4096, 512), fp16 hi only
__global__ void __launch_bounds__(256) tconv_kernel(const float* __restrict__ in,
                                                    __half* __restrict__ oh) {
    __shared__ float T[32][33];
    const int tx = threadIdx.x & 31, ty = threadIdx.x >> 5;
    const int x0 = blockIdx.x * 32, c0 = blockIdx.y * 32;
    const float* I = in + (size_t)blockIdx.z * CH * HW;
    #pragma unroll
    for (int r = 0; r < 4; r++)
        T[ty + r * 8][tx] = I[(size_t)(c0 + ty + r * 8) * HW + x0 + tx];
    __syncthreads();
    const size_t ob = (size_t)blockIdx.z * HW * CH;
    #pragma unroll
    for (int r = 0; r < 4; r++) {
        const size_t o = ob + (size_t)(x0 + ty + r * 8) * CH + c0 + tx;
        oh[o] = __float2half(T[tx][ty + r * 8]);
    }
}

// row softmax (rows of length 2048) -> fp16
__global__ void __launch_bounds__(256) softmax_h_kernel(const float* __restrict__ S,
                                                        __half* __restrict__ Sh) {
    const size_t row = blockIdx.x;
    const float* p = S + row * HW2;
    const int tid = threadIdx.x;

    float4 v0 = ((const float4*)p)[tid];
    float4 v1 = ((const float4*)p)[tid + 256];

    float mx = fmaxf(fmaxf(fmaxf(v0.x, v0.y), fmaxf(v0.z, v0.w)),
                     fmaxf(fmaxf(v1.x, v1.y), fmaxf(v1.z, v1.w)));
    __shared__ float red[8];
    #pragma unroll
    for (int o = 16; o > 0; o >>= 1) mx = fmaxf(mx, __shfl_xor_sync(0xffffffffu, mx, o));
    if ((tid & 31) == 0) red[tid >> 5] = mx;
    __syncthreads();
    mx = red[0];
    #pragma unroll
    for (int i = 1; i < 8; i++) mx = fmaxf(mx, red[i]);
    __syncthreads();

    v0.x = __expf(v0.x - mx); v0.y = __expf(v0.y - mx);
    v0.z = __expf(v0.z - mx); v0.w = __expf(v0.w - mx);
    v1.x = __expf(v1.x - mx); v1.y = __expf(v1.y - mx);
    v1.z = __expf(v1.z - mx); v1.w = __expf(v1.w - mx);

    float sum = v0.x + v0.y + v0.z + v0.w + v1.x + v1.y + v1.z + v1.w;
    #pragma unroll
    for (int o = 16; o > 0; o >>= 1) sum += __shfl_xor_sync(0xffffffffu, sum, o);
    if ((tid & 31) == 0) red[tid >> 5] = sum;
    __syncthreads();
    sum = red[0];
    #pragma unroll
    for (int i = 1; i < 8; i++) sum += red[i];

    const float inv = 1.0f / sum;
    __half2* ph = (__half2*)(Sh + row * HW2);
    ph[tid * 2 + 0] = __halves2half2(__float2half(v0.x * inv), __float2half(v0.y * inv));
    ph[tid * 2 + 1] = __halves2half2(__float2half(v0.z * inv), __float2half(v0.w * inv));
    ph[(tid + 256) * 2 + 0] = __halves2half2(__float2half(v1.x * inv), __float2half(v1.y * inv));
    ph[(tid + 256) * 2 + 1] = __halves2half2(__float2half(v1.z * inv), __float2half(v1.w * inv));
}

// ---------------------------------------------------------------------------
extern "C" void kernel_launch(void* const* d_in, const int* in_sizes, int n_in,
                              void* d_out, int out_size)
{
    const float* q    = (const float*)d_in[0];
    const float* k    = (const float*)d_in[1];
    const float* v    = (const float*)d_in[2];
    const float* Wphi = (const float*)d_in[3];
    const float* Wth  = (const float*)d_in[4];
    const float* Wg   = (const float*)d_in[5];
    const float* Wm   = (const float*)d_in[6];
    float* out = (float*)d_out;

    constexpr int SMEM = 98304;   // 3 stages x 32 KB stride (epilogue reuses)
    cudaFuncSetAttribute(mma_gemm<3,2>, cudaFuncAttributeMaxDynamicSharedMemorySize, SMEM);
    cudaFuncSetAttribute(mma_gemm<5,2>, cudaFuncAttributeMaxDynamicSharedMemorySize, SMEM);
    cudaFuncSetAttribute(mma_gemm<1,1>, cudaFuncAttributeMaxDynamicSharedMemorySize, SMEM);
    cudaFuncSetAttribute(mma_gemm<0,2>, cudaFuncAttributeMaxDynamicSharedMemorySize, SMEM);
    cudaFuncSetAttribute(mma_gemm<4,1>, cudaFuncAttributeMaxDynamicSharedMemorySize, SMEM);
    cudaFuncSetAttribute(mma_gemm<2,1>, cudaFuncAttributeMaxDynamicSharedMemorySize, SMEM);

    float* S;
    cudaGetSymbolAddress((void**)&S, g_S);
    __half *qTh, *kTh, *vTh;
    __half *Wph, *Wpl, *Wthh, *Wtl, *Wgh, *Wgl, *Wmh, *Wml;
    __half *gh, *pTh, *pTl, *tTh, *Sh, *y3h;
    cudaGetSymbolAddress((void**)&qTh, g_qTh);
    cudaGetSymbolAddress((void**)&kTh, g_kTh);
    cudaGetSymbolAddress((void**)&vTh, g_vTh);
    cudaGetSymbolAddress((void**)&Wph, g_Wph); cudaGetSymbolAddress((void**)&Wpl, g_Wpl);
    cudaGetSymbolAddress((void**)&Wthh, g_Wth); cudaGetSymbolAddress((void**)&Wtl, g_Wtl);
    cudaGetSymbolAddress((void**)&Wgh, g_Wgh); cudaGetSymbolAddress((void**)&Wgl, g_Wgl);
    cudaGetSymbolAddress((void**)&Wmh, g_Wmh); cudaGetSymbolAddress((void**)&Wml, g_Wml);
    cudaGetSymbolAddress((void**)&gh, g_gh);
    cudaGetSymbolAddress((void**)&pTh, g_pTh); cudaGetSymbolAddress((void**)&pTl, g_pTl);
    cudaGetSymbolAddress((void**)&tTh, g_tTh);
    cudaGetSymbolAddress((void**)&Sh, g_Sh);
    cudaGetSymbolAddress((void**)&y3h, g_y3h);

    const dim3 blk(256);
    const long long sX  = (long long)CH * HW;    // q/k/v/out batch stride
    const long long sT  = (long long)HW * CH;    // qT/kT/vT
    const long long sP  = (long long)CO * HW;    // g (==CH*HW2)
    const long long sPT = (long long)HW2 * CH;   // pT/tT
    const long long sS  = (long long)HW2 * HW2;  // scores
    const long long sY3 = (long long)HW * CO;    // y3

    // 0) weight splits (one launch)
    split4_kernel<<<dim3(CO * CH / 256, 4), blk>>>(Wphi, Wth, Wg, Wm,
                                                   Wph, Wpl, Wthh, Wtl,
                                                   Wgh, Wgl, Wmh, Wml);

    // 1) input transposes -> fp16 hi
    tconv_kernel<<<dim3(HW / 32, CH / 32, NB), blk>>>(q, qTh);
    tconv_kernel<<<dim3(HW / 32, CH / 32, NB), blk>>>(k, kTh);
    tconv_kernel<<<dim3(HW / 32, CH / 32, NB), blk>>>(v, vTh);

    // 2) 1x1 convs: phi (2-term, EPI=3 hi+lo transposed), theta (2-term, EPI=5 hi),
    //    g (1-term, EPI=1 row-major hi)
    mma_gemm<3,2><<<dim3(HW / 128, CO / 128, NB), blk, SMEM>>>(Wph, Wpl, qTh, nullptr, pTh, pTl,
                                                               CH, CH, 0, sT, sPT, nullptr, nullptr);
    mma_gemm<5,2><<<dim3(HW / 128, CO / 128, NB), blk, SMEM>>>(Wthh, Wtl, kTh, nullptr, tTh, nullptr,
                                                               CH, CH, 0, sT, sPT, nullptr, nullptr);
    mma_gemm<1,1><<<dim3(HW / 128, CO / 128, NB), blk, SMEM>>>(Wgh, nullptr, vTh, nullptr, gh, nullptr,
                                                               CH, HW, 0, sT, sP, nullptr, nullptr);

    // 3) scores (2-term): S[m,n] = sum_k' pT[m,k'] * tT[n,k']
    mma_gemm<0,2><<<dim3(HW2 / 128, HW2 / 128, NB), blk, SMEM>>>(pTh, pTl, tTh, S, nullptr, nullptr,
                                                                 CH, HW2, sPT, sPT, sS, nullptr, nullptr);

    // 4) row softmax -> fp16
    softmax_h_kernel<<<NB * HW2, blk>>>(S, Sh);

    // 5) attn apply (1-term, EPI=4): writes y3h transposed directly
    mma_gemm<4,1><<<dim3(HW2 / 128, CH / 128, NB), blk, SMEM>>>(gh, nullptr, Sh, nullptr, y3h, nullptr,
                                                                HW2, CO, sP, sS, sY3, nullptr, nullptr);

    // 6) mask conv (1-term) + residual: out = Wm @ y3 + q + v
    mma_gemm<2,1><<<dim3(HW / 128, CH / 128, NB), blk, SMEM>>>(Wmh, nullptr, y3h, out, nullptr, nullptr,
                                                               CO, HW, 0, sY3, sX, q, v);
}

// round 11
// speedup vs baseline: 1.6587x; 1.0204x over previous
#include <cuda_runtime.h>
#include <cuda_fp16.h>
#include <cstdint>

constexpr int NB  = 8;
constexpr int CH  = 512;
constexpr int HW  = 4096;
constexpr int HW2 = 2048;
constexpr int CO  = 256;

// ---------------- device scratch ----------------
__device__ __align__(256) float g_S [(size_t)NB * HW2 * HW2];

__device__ __align__(256) __half g_qTh[(size_t)NB * HW * CH];
__device__ __align__(256) __half g_kTh[(size_t)NB * HW * CH];
__device__ __align__(256) __half g_vTh[(size_t)NB * HW * CH];
__device__ __align__(256) __half g_Wph[CO * CH], g_Wpl[CO * CH];
__device__ __align__(256) __half g_Wth[CO * CH], g_Wtl[CO * CH];
__device__ __align__(256) __half g_Wgh[CO * CH], g_Wgl[CO * CH];
__device__ __align__(256) __half g_Wmh[CH * CO], g_Wml[CH * CO];
__device__ __align__(256) __half g_gh [(size_t)NB * CH * HW2];
__device__ __align__(256) __half g_pTh[(size_t)NB * HW2 * CH], g_pTl[(size_t)NB * HW2 * CH];
__device__ __align__(256) __half g_tTh[(size_t)NB * HW2 * CH];
__device__ __align__(256) __half g_Sh [(size_t)NB * HW2 * HW2];
__device__ __align__(256) __half g_y3h[(size_t)NB * HW * CO];

// ---------------- helpers ----------------
__device__ __forceinline__ uint32_t s2u(const void* p) {
    uint32_t a;
    asm("{ .reg .u64 t; cvta.to.shared.u64 t, %1; cvt.u32.u64 %0, t; }" : "=r"(a) : "l"(p));
    return a;
}
__device__ __forceinline__ void hsplit(float v, __half& h, __half& l) {
    h = __float2half(v);
    l = __float2half(v - __half2float(h));
}
__device__ __forceinline__ void ldsm4(uint32_t* r, uint32_t addr) {
    asm volatile("ldmatrix.sync.aligned.m8n8.x4.shared.b16 {%0,%1,%2,%3}, [%4];"
                 : "=r"(r[0]), "=r"(r[1]), "=r"(r[2]), "=r"(r[3]) : "r"(addr));
}
__device__ __forceinline__ void mma16816(float* d, const uint32_t* a, uint32_t b0, uint32_t b1) {
    asm volatile("mma.sync.aligned.m16n8k16.row.col.f32.f16.f16.f32 "
                 "{%0,%1,%2,%3}, {%4,%5,%6,%7}, {%8,%9}, {%0,%1,%2,%3};"
                 : "+f"(d[0]), "+f"(d[1]), "+f"(d[2]), "+f"(d[3])
                 : "r"(a[0]), "r"(a[1]), "r"(a[2]), "r"(a[3]), "r"(b0), "r"(b1));
}
__device__ __forceinline__ void cpasync16(uint32_t s, const void* g) {
    asm volatile("cp.async.cg.shared.global [%0], [%1], 16;" :: "r"(s), "l"(g));
}
#define CP_COMMIT() asm volatile("cp.async.commit_group;" ::: "memory")
#define CP_WAIT1()  asm volatile("cp.async.wait_group 1;" ::: "memory")
#define CP_WAIT0()  asm volatile("cp.async.wait_group 0;" ::: "memory")

// smem per stage (32 KB stride): Ah @0, Al @8192 (TERMS==2 only), Bh @16384.
// Row = 64 B (32 fp16), chunk = 16 B, swizzle: chunk ^= (row>>1)&3
template <int TERMS>
__device__ __forceinline__ void load_stage(uint32_t sbase,
    const __half* pAh, const __half* pAl, const __half* pBh,
    int Ktot, int kofs, int tid)
{
    const int row = tid >> 1;
    const int c0 = (tid & 1) * 2;
    const long long gofs = (long long)row * Ktot + kofs;
    #pragma unroll
    for (int s = 0; s < 2; s++) {
        const int c = c0 + s;
        const uint32_t soff = row * 64 + ((c ^ ((row >> 1) & 3)) << 4);
        cpasync16(sbase +         soff, pAh + gofs + c * 8);
        if (TERMS == 2)
            cpasync16(sbase + 8192 + soff, pAl + gofs + c * 8);
        cpasync16(sbase + 16384 + soff, pBh + gofs + c * 8);
    }
}

// ---------------------------------------------------------------------------
// Split-fp16 tensor-core GEMM (mma.sync), 3-stage cp.async pipeline.
// D(128x128 fp32 tile) = (Ah[+Al])(MxK) @ Bh^T(NxK), fp16 K-major.
// TERMS: 2 = hh + lh; 1 = hh only. (B lo never exists.)
// Inner loop issues ALL hi-MMAs then ALL lo-MMAs: per-accumulator dependency
// distance 16 instructions (was 2) -> hide HMMA latency.
// EPI: 0 = fp32 store (scores)
//      1 = row-major hi store (g conv)
//      2 = fp32 + r1 + r2 residual (mask)
//      3 = transposed hi+lo store, k' = h1*256+o (phi conv -> pT)
//      5 = transposed hi store,    k' = h1*256+o (theta conv -> tT)
//      4 = transposed hi store, parity-grouped cols (apply -> y3)
// ---------------------------------------------------------------------------
template <int EPI, int TERMS>
__global__ void __launch_bounds__(256, 2) mma_gemm(
    const __half* __restrict__ Ah, const __half* __restrict__ Al,
    const __half* __restrict__ Bh,
    float* __restrict__ C, __half* __restrict__ Ch, __half* __restrict__ Cl,
    int Ktot, int ldc,
    long long sA, long long sB, long long sC,
    const float* __restrict__ r1, const float* __restrict__ r2)
{
    extern __shared__ __align__(1024) char sm[];
    const int tid = threadIdx.x;
    const int wid = tid >> 5, lane = tid & 31;
    const uint32_t sb = s2u(sm);

    const int m0 = blockIdx.y * 128;
    const int n0 = blockIdx.x * 128;
    const long long bz = blockIdx.z;

    const __half* pAh = Ah + bz * sA + (long long)m0 * Ktot;
    const __half* pAl = (TERMS == 2) ? (Al + bz * sA + (long long)m0 * Ktot) : nullptr;
    const __half* pBh = Bh + bz * sB + (long long)n0 * Ktot;

    const int wm = (wid >> 1) * 32;
    const int wn = (wid & 1) * 64;

    float acc[2][8][4];
    #pragma unroll
    for (int i = 0; i < 2; i++)
        #pragma unroll
        for (int j = 0; j < 8; j++)
            #pragma unroll
            for (int t = 0; t < 4; t++) acc[i][j][t] = 0.0f;

    const int nch = Ktot >> 5;
    load_stage<TERMS>(sb, pAh, pAl, pBh, Ktot, 0, tid);
    CP_COMMIT();
    load_stage<TERMS>(sb + 32768, pAh, pAl, pBh, Ktot, 32, tid);
    CP_COMMIT();

    uint32_t stage = 0;
    uint32_t nstage = 2;
    for (int ic = 0; ic < nch; ic++) {
        CP_WAIT1();
        __syncthreads();
        if (ic + 2 < nch) {
            load_stage<TERMS>(sb + nstage * 32768, pAh, pAl, pBh,
                              Ktot, (ic + 2) << 5, tid);
        }
        CP_COMMIT();
        nstage = (nstage == 2) ? 0 : nstage + 1;

        const uint32_t st = sb + stage * 32768;
        stage = (stage == 2) ? 0 : stage + 1;
        #pragma unroll
        for (int kk = 0; kk < 32; kk += 16) {
            const int kc = (kk >> 3) + (lane >> 4);
            uint32_t a_h[2][4], a_l[2][4], b_all[4][4];
            #pragma unroll
            for (int mi = 0; mi < 2; mi++) {
                const int row = wm + mi * 16 + (lane & 15);
                const uint32_t ad = st + row * 64 + ((kc ^ ((row >> 1) & 3)) << 4);
                ldsm4(a_h[mi], ad);
                if (TERMS == 2) ldsm4(a_l[mi], ad + 8192);
            }
            #pragma unroll
            for (int jj = 0; jj < 4; jj++) {
                const int row = wn + jj * 16 + (lane & 15);
                const uint32_t bd = st + 16384 + row * 64 + ((kc ^ ((row >> 1) & 3)) << 4);
                ldsm4(b_all[jj], bd);
            }
            // hi pass: 16 independent MMAs
            #pragma unroll
            for (int jj = 0; jj < 4; jj++)
                #pragma unroll
                for (int mi = 0; mi < 2; mi++) {
                    mma16816(acc[mi][jj * 2],     a_h[mi], b_all[jj][0], b_all[jj][2]);
                    mma16816(acc[mi][jj * 2 + 1], a_h[mi], b_all[jj][1], b_all[jj][3]);
                }
            // lo pass: 16 independent MMAs, each 16 instructions after its hi
            if (TERMS == 2) {
                #pragma unroll
                for (int jj = 0; jj < 4; jj++)
                    #pragma unroll
                    for (int mi = 0; mi < 2; mi++) {
                        mma16816(acc[mi][jj * 2],     a_l[mi], b_all[jj][0], b_all[jj][2]);
                        mma16816(acc[mi][jj * 2 + 1], a_l[mi], b_all[jj][1], b_all[jj][3]);
                    }
            }
        }
    }

    const int g = lane >> 2, tg = lane & 3;
    const long long cbz = bz * sC;

    if (EPI == 3 || EPI == 4 || EPI == 5) {
        // stage tile fp32 in smem [row(m) * 129 + col(n)], transposed coalesced stores
        CP_WAIT0();
        __syncthreads();
        float* Dsm = (float*)sm;
        #pragma unroll
        for (int mi = 0; mi < 2; mi++)
            #pragma unroll
            for (int j = 0; j < 8; j++)
                #pragma unroll
                for (int h = 0; h < 2; h++) {
                    const int row = wm + mi * 16 + g + h * 8;
                    const int col = wn + j * 8 + tg * 2;
                    Dsm[row * 129 + col]     = acc[mi][j][h * 2];
                    Dsm[row * 129 + col + 1] = acc[mi][j][h * 2 + 1];
                }
        __syncthreads();

        if (EPI == 3 || EPI == 5) {
            // out[n][h1*256 + o]; row = 128 fp16 = 256B = 16 lanes x 16B.
            const int h1 = n0 >> 11;
            const int xb = n0 & 2047;
            const int lane16 = lane & 15;
            const int sub = lane >> 4;                 // 2 rows per warp per pass
            #pragma unroll
            for (int p = 0; p < 8; p++) {
                const int n_loc = p * 16 + wid * 2 + sub;
                __align__(16) __half hbuf[8], lbuf[8];
                #pragma unroll
                for (int j = 0; j < 8; j++) {
                    if (EPI == 3) hsplit(Dsm[(lane16 * 8 + j) * 129 + n_loc], hbuf[j], lbuf[j]);
                    else          hbuf[j] = __float2half(Dsm[(lane16 * 8 + j) * 129 + n_loc]);
                }
                const long long ob = cbz + (long long)(xb + n_loc) * ldc
                                   + h1 * 256 + m0 + lane16 * 8;
                *(uint4*)(Ch + ob) = *(uint4*)hbuf;
                if (EPI == 3) *(uint4*)(Cl + ob) = *(uint4*)lbuf;
            }
        } else {
            // y3[h1*2048 + n0 + m][m0/2 + o2]; row = 64 fp16 = 128B = 8 lanes x 16B.
            const int lane8 = lane & 7;
            const int rsub = lane >> 3;                // 4 rows per warp per pass
            #pragma unroll
            for (int p = 0; p < 8; p++) {
                const int R = p * 32 + wid * 4 + rsub; // 0..255
                const int h1 = R >> 7;
                const int m_loc = R & 127;
                __align__(16) __half hbuf[8];
                #pragma unroll
                for (int j = 0; j < 8; j++)
                    hbuf[j] = __float2half(Dsm[(2 * (lane8 * 8 + j) + h1) * 129 + m_loc]);
                const long long ob = cbz + (long long)(h1 * 2048 + n0 + m_loc) * ldc
                                   + (m0 >> 1) + lane8 * 8;
                *(uint4*)(Ch + ob) = *(uint4*)hbuf;
            }
        }
        return;
    }

    // direct epilogues (0/1/2)
    #pragma unroll
    for (int mi = 0; mi < 2; mi++) {
        #pragma unroll
        for (int j = 0; j < 8; j++) {
            const int row = m0 + wm + mi * 16 + g;
            const int col = n0 + wn + j * 8 + tg * 2;
            #pragma unroll
            for (int h = 0; h < 2; h++) {
                const long long idx = cbz + (long long)(row + h * 8) * ldc + col;
                const float d0 = acc[mi][j][h * 2];
                const float d1 = acc[mi][j][h * 2 + 1];
                if (EPI == 0) {
                    *(float2*)(C + idx) = make_float2(d0, d1);
                } else if (EPI == 2) {
                    const float2 a = *(const float2*)(r1 + idx);
                    const float2 b = *(const float2*)(r2 + idx);
                    *(float2*)(C + idx) = make_float2(d0 + a.x + b.x, d1 + a.y + b.y);
                } else {
                    *(__half2*)(Ch + idx) =
                        __halves2half2(__float2half(d0), __float2half(d1));
                }
            }
        }
    }
}

// ---------------------------------------------------------------------------
// conversion kernels
// ---------------------------------------------------------------------------
// all 4 weight splits in one launch
__global__ void __launch_bounds__(256) split4_kernel(
    const float* __restrict__ s0, const float* __restrict__ s1,
    const float* __restrict__ s2, const float* __restrict__ s3,
    __half* __restrict__ h0, __half* __restrict__ l0,
    __half* __restrict__ h1, __half* __restrict__ l1,
    __half* __restrict__ h2, __half* __restrict__ l2,
    __half* __restrict__ h3, __half* __restrict__ l3)
{
    const int i = blockIdx.x * 256 + threadIdx.x;
    const int wsel = blockIdx.y;
    const float* s = (wsel == 0) ? s0 : (wsel == 1) ? s1 : (wsel == 2) ? s2 : s3;
    __half* hh = (wsel == 0) ? h0 : (wsel == 1) ? h1 : (wsel == 2) ? h2 : h3;
    __half* ll = (wsel == 0) ? l0 : (wsel == 1) ? l1 : (wsel == 2) ? l2 : l3;
    __half h, l;
    hsplit(s[i], h, l);
    hh[i] = h; ll[i] = l;
}

// (b, 512, 4096) -> (b, 4096, 512), fp16 hi only
__global__ void __launch_bounds__(256) tconv_kernel(const float* __restrict__ in,
                                                    __half* __restrict__ oh) {
    __shared__ float T[32][33];
    const int tx = threadIdx.x & 31, ty = threadIdx.x >> 5;
    const int x0 = blockIdx.x * 32, c0 = blockIdx.y * 32;
    const float* I = in + (size_t)blockIdx.z * CH * HW;
    #pragma unroll
    for (int r = 0; r < 4; r++)
        T[ty + r * 8][tx] = I[(size_t)(c0 + ty + r * 8) * HW + x0 + tx];
    __syncthreads();
    const size_t ob = (size_t)blockIdx.z * HW * CH;
    #pragma unroll
    for (int r = 0; r < 4; r++) {
        const size_t o = ob + (size_t)(x0 + ty + r * 8) * CH + c0 + tx;
        oh[o] = __float2half(T[tx][ty + r * 8]);
    }
}

// row softmax (rows of length 2048) -> fp16
__global__ void __launch_bounds__(256) softmax_h_kernel(const float* __restrict__ S,
                                                        __half* __restrict__ Sh) {
    const size_t row = blockIdx.x;
    const float* p = S + row * HW2;
    const int tid = threadIdx.x;

    float4 v0 = ((const float4*)p)[tid];
    float4 v1 = ((const float4*)p)[tid + 256];

    float mx = fmaxf(fmaxf(fmaxf(v0.x, v0.y), fmaxf(v0.z, v0.w)),
                     fmaxf(fmaxf(v1.x, v1.y), fmaxf(v1.z, v1.w)));
    __shared__ float red[8];
    #pragma unroll
    for (int o = 16; o > 0; o >>= 1) mx = fmaxf(mx, __shfl_xor_sync(0xffffffffu, mx, o));
    if ((tid & 31) == 0) red[tid >> 5] = mx;
    __syncthreads();
    mx = red[0];
    #pragma unroll
    for (int i = 1; i < 8; i++) mx = fmaxf(mx, red[i]);
    __syncthreads();

    v0.x = __expf(v0.x - mx); v0.y = __expf(v0.y - mx);
    v0.z = __expf(v0.z - mx); v0.w = __expf(v0.w - mx);
    v1.x = __expf(v1.x - mx); v1.y = __expf(v1.y - mx);
    v1.z = __expf(v1.z - mx); v1.w = __expf(v1.w - mx);

    float sum = v0.x + v0.y + v0.z + v0.w + v1.x + v1.y + v1.z + v1.w;
    #pragma unroll
    for (int o = 16; o > 0; o >>= 1) sum += __shfl_xor_sync(0xffffffffu, sum, o);
    if ((tid & 31) == 0) red[tid >> 5] = sum;
    __syncthreads();
    sum = red[0];
    #pragma unroll
    for (int i = 1; i < 8; i++) sum += red[i];

    const float inv = 1.0f / sum;
    __half2* ph = (__half2*)(Sh + row * HW2);
    ph[tid * 2 + 0] = __halves2half2(__float2half(v0.x * inv), __float2half(v0.y * inv));
    ph[tid * 2 + 1] = __halves2half2(__float2half(v0.z * inv), __float2half(v0.w * inv));
    ph[(tid + 256) * 2 + 0] = __halves2half2(__float2half(v1.x * inv), __float2half(v1.y * inv));
    ph[(tid + 256) * 2 + 1] = __halves2half2(__float2half(v1.z * inv), __float2half(v1.w * inv));
}

// ---------------------------------------------------------------------------
extern "C" void kernel_launch(void* const* d_in, const int* in_sizes, int n_in,
                              void* d_out, int out_size)
{
    const float* q    = (const float*)d_in[0];
    const float* k    = (const float*)d_in[1];
    const float* v    = (const float*)d_in[2];
    const float* Wphi = (const float*)d_in[3];
    const float* Wth  = (const float*)d_in[4];
    const float* Wg   = (const float*)d_in[5];
    const float* Wm   = (const float*)d_in[6];
    float* out = (float*)d_out;

    constexpr int SMEM = 98304;   // 3 stages x 32 KB stride (epilogue reuses)
    cudaFuncSetAttribute(mma_gemm<3,2>, cudaFuncAttributeMaxDynamicSharedMemorySize, SMEM);
    cudaFuncSetAttribute(mma_gemm<5,2>, cudaFuncAttributeMaxDynamicSharedMemorySize, SMEM);
    cudaFuncSetAttribute(mma_gemm<1,1>, cudaFuncAttributeMaxDynamicSharedMemorySize, SMEM);
    cudaFuncSetAttribute(mma_gemm<0,2>, cudaFuncAttributeMaxDynamicSharedMemorySize, SMEM);
    cudaFuncSetAttribute(mma_gemm<4,1>, cudaFuncAttributeMaxDynamicSharedMemorySize, SMEM);
    cudaFuncSetAttribute(mma_gemm<2,1>, cudaFuncAttributeMaxDynamicSharedMemorySize, SMEM);

    float* S;
    cudaGetSymbolAddress((void**)&S, g_S);
    __half *qTh, *kTh, *vTh;
    __half *Wph, *Wpl, *Wthh, *Wtl, *Wgh, *Wgl, *Wmh, *Wml;
    __half *gh, *pTh, *pTl, *tTh, *Sh, *y3h;
    cudaGetSymbolAddress((void**)&qTh, g_qTh);
    cudaGetSymbolAddress((void**)&kTh, g_kTh);
    cudaGetSymbolAddress((void**)&vTh, g_vTh);
    cudaGetSymbolAddress((void**)&Wph, g_Wph); cudaGetSymbolAddress((void**)&Wpl, g_Wpl);
    cudaGetSymbolAddress((void**)&Wthh, g_Wth); cudaGetSymbolAddress((void**)&Wtl, g_Wtl);
    cudaGetSymbolAddress((void**)&Wgh, g_Wgh); cudaGetSymbolAddress((void**)&Wgl, g_Wgl);
    cudaGetSymbolAddress((void**)&Wmh, g_Wmh); cudaGetSymbolAddress((void**)&Wml, g_Wml);
    cudaGetSymbolAddress((void**)&gh, g_gh);
    cudaGetSymbolAddress((void**)&pTh, g_pTh); cudaGetSymbolAddress((void**)&pTl, g_pTl);
    cudaGetSymbolAddress((void**)&tTh, g_tTh);
    cudaGetSymbolAddress((void**)&Sh, g_Sh);
    cudaGetSymbolAddress((void**)&y3h, g_y3h);

    const dim3 blk(256);
    const long long sX  = (long long)CH * HW;    // q/k/v/out batch stride
    const long long sT  = (long long)HW * CH;    // qT/kT/vT
    const long long sP  = (long long)CO * HW;    // g (==CH*HW2)
    const long long sPT = (long long)HW2 * CH;   // pT/tT
    const long long sS  = (long long)HW2 * HW2;  // scores
    const long long sY3 = (long long)HW * CO;    // y3

    // Order chosen so the ncu capture slot (~launch 4-6) lands on a GEMM.
    // 0) weight splits (one launch)
    split4_kernel<<<dim3(CO * CH / 256, 4), blk>>>(Wphi, Wth, Wg, Wm,
                                                   Wph, Wpl, Wthh, Wtl,
                                                   Wgh, Wgl, Wmh, Wml);

    // 1) q/k transposes -> fp16 hi
    tconv_kernel<<<dim3(HW / 32, CH / 32, NB), blk>>>(q, qTh);
    tconv_kernel<<<dim3(HW / 32, CH / 32, NB), blk>>>(k, kTh);

    // 2) phi/theta convs (2-term, transposed epilogues)
    mma_gemm<3,2><<<dim3(HW / 128, CO / 128, NB), blk, SMEM>>>(Wph, Wpl, qTh, nullptr, pTh, pTl,
                                                               CH, CH, 0, sT, sPT, nullptr, nullptr);
    mma_gemm<5,2><<<dim3(HW / 128, CO / 128, NB), blk, SMEM>>>(Wthh, Wtl, kTh, nullptr, tTh, nullptr,
                                                               CH, CH, 0, sT, sPT, nullptr, nullptr);

    // 3) scores (2-term): S[m,n] = sum_k' pT[m,k'] * tT[n,k']
    mma_gemm<0,2><<<dim3(HW2 / 128, HW2 / 128, NB), blk, SMEM>>>(pTh, pTl, tTh, S, nullptr, nullptr,
                                                                 CH, HW2, sPT, sPT, sS, nullptr, nullptr);

    // 4) v transpose + g conv (independent of scores; overlap the tail)
    tconv_kernel<<<dim3(HW / 32, CH / 32, NB), blk>>>(v, vTh);
    mma_gemm<1,1><<<dim3(HW / 128, CO / 128, NB), blk, SMEM>>>(Wgh, nullptr, vTh, nullptr, gh, nullptr,
                                                               CH, HW, 0, sT, sP, nullptr, nullptr);

    // 5) row softmax -> fp16
    softmax_h_kernel<<<NB * HW2, blk>>>(S, Sh);

    // 6) attn apply (1-term, EPI=4): writes y3h transposed directly
    mma_gemm<4,1><<<dim3(HW2 / 128, CH / 128, NB), blk, SMEM>>>(gh, nullptr, Sh, nullptr, y3h, nullptr,
                                                                HW2, CO, sP, sS, sY3, nullptr, nullptr);

    // 7) mask conv (1-term) + residual: out = Wm @ y3 + q + v
    mma_gemm<2,1><<<dim3(HW / 128, CH / 128, NB), blk, SMEM>>>(Wmh, nullptr, y3h, out, nullptr, nullptr,
                                                               CO, HW, 0, sY3, sX, q, v);
}